// round 5
// baseline (speedup 1.0000x reference)
#include <cuda_runtime.h>
#include <math.h>
#include <stdint.h>

#define NFEAT 64
#define DIM   256
#define NHEAD 8
#define HDIM  32
#define XS    260   // padded x row stride (floats)
#define QS    36    // qh row stride
#define ATS   68    // att row stride

#define CHUNK_K   16
#define NCHUNK    (DIM / CHUNK_K)       // 16
#define WB_FLOATS (CHUNK_K * 96)        // 1536 per buffer

#define SMEM_FLOATS (NFEAT*XS + NFEAT*QS + 2048 + 2048 + NFEAT*ATS + 256)

typedef unsigned long long u64;

__device__ __forceinline__ void ffma2(u64& d, u64 a, u64 b) {
    asm("fma.rn.f32x2 %0, %1, %2, %0;" : "+l"(d) : "l"(a), "l"(b));
}
__device__ __forceinline__ u64 dup2(float v) {
    u64 r; asm("mov.b64 %0, {%1, %1};" : "=l"(r) : "f"(v)); return r;
}
__device__ __forceinline__ float2 unpk(u64 v) {
    float lo, hi; asm("mov.b64 {%0, %1}, %2;" : "=f"(lo), "=f"(hi) : "l"(v));
    return make_float2(lo, hi);
}
__device__ __forceinline__ uint32_t s2u(const void* p) {
    uint32_t a;
    asm("{ .reg .u64 t; cvta.to.shared.u64 t, %1; cvt.u32.u64 %0, t; }"
        : "=r"(a) : "l"(p));
    return a;
}
#define CP16(dst, src) \
    asm volatile("cp.async.cg.shared.global [%0], [%1], 16;" :: "r"(dst), "l"(src))
#define CPCOMMIT() asm volatile("cp.async.commit_group;" ::: "memory")
#define CPWAIT1()  asm volatile("cp.async.wait_group 1;"  ::: "memory")

__global__ __launch_bounds__(256, 2)
void autoint_kernel(const float* __restrict__ x,
                    const float* __restrict__ Wq, const float* __restrict__ bq,
                    const float* __restrict__ Wk, const float* __restrict__ bk,
                    const float* __restrict__ Wv, const float* __restrict__ bv,
                    const float* __restrict__ W1, const float* __restrict__ b1,
                    const float* __restrict__ W2, const float* __restrict__ b2,
                    float* __restrict__ out)
{
    extern __shared__ float sm[];
    float* xs  = sm;                   // 64*260
    float* qh  = xs + NFEAT * XS;      // 64*36
    float* kt  = qh + NFEAT * QS;      // 32*64 (k transposed; reused as zh 64*32)
    float* vh  = kt + 2048;            // 64*32
    float* att = vh + 2048;            // 64*68 (aliased by weight staging buf)
    float* red = att + NFEAT * ATS;    // 256
    float* wbuf = att;                 // 2 x 1536 floats <= 4352
    const uint32_t wbuf_u = s2u(wbuf);

    const int t = threadIdx.x;
    const int b = blockIdx.x;
    const float* xg = x + (size_t)b * (NFEAT * DIM);

    // ---- staging descriptors (per-thread, head-invariant) ----
    // chunk = 384 float4 covering [16k x 96cols]; thread handles e = t (+256 if t<128)
    const float* sbase[2];
    int doff[2];
    const int nst = (t < 128) ? 2 : 1;
#pragma unroll
    for (int s = 0; s < 2; s++) {
        int e   = t + s * 256;
        int kl  = e / 24;
        int r   = e - kl * 24;
        int mat = r >> 3;
        int c4s = (r & 7) << 2;
        const float* W = (mat == 0) ? Wq : (mat == 1) ? Wk : Wv;
        sbase[s] = W + kl * DIM + c4s;
        doff[s]  = kl * 96 + mat * 32 + c4s;
    }

    // ---- load x ----
    {
        const float4* xg4 = (const float4*)xg;
#pragma unroll
        for (int n = t; n < NFEAT * DIM / 4; n += 256) {
            float4 v = xg4[n];
            *(float4*)&xs[(n >> 6) * XS + ((n & 63) << 2)] = v;
        }
    }
    __syncthreads();

    const float inv_sqrt_d = 0.17677669529663687f; // 1/sqrt(32)

    u64 facc[16][2];
#pragma unroll
    for (int r = 0; r < 16; r++) { facc[r][0] = 0ull; facc[r][1] = 0ull; }

    for (int h = 0; h < NHEAD; h++) {
        const int hd = h * HDIM;

        // ==== fused q/k/v head projections with cp.async weight staging ====
        // thread tile: 2 rows (i0) x 4 cols (c4) x 3 matrices
        {
            const int c4 = (t & 7) << 2;
            const int i0 = (t >> 3) << 1;
            u64 aq[2][2] = {{0ull,0ull},{0ull,0ull}};
            u64 ak[2][2] = {{0ull,0ull},{0ull,0ull}};
            u64 av[2][2] = {{0ull,0ull},{0ull,0ull}};

            // prefetch chunks 0 and 1
#pragma unroll
            for (int c = 0; c < 2; c++) {
                for (int s = 0; s < nst; s++)
                    CP16(wbuf_u + (uint32_t)((c * WB_FLOATS + doff[s]) * 4),
                         sbase[s] + hd + c * CHUNK_K * DIM);
                CPCOMMIT();
            }

            for (int ch = 0; ch < NCHUNK; ch++) {
                CPWAIT1();
                __syncthreads();
                const float* wb = wbuf + (ch & 1) * WB_FLOATS;
                const int kb = ch * CHUNK_K;
#pragma unroll
                for (int kk = 0; kk < CHUNK_K; kk += 4) {
                    float4 x0 = *(const float4*)&xs[(i0+0)*XS + kb + kk];
                    float4 x1 = *(const float4*)&xs[(i0+1)*XS + kb + kk];
                    float xk0[4] = {x0.x, x0.y, x0.z, x0.w};
                    float xk1[4] = {x1.x, x1.y, x1.z, x1.w};
#pragma unroll
                    for (int kq = 0; kq < 4; kq++) {
                        const float* wr = wb + (kk + kq) * 96 + c4;
                        ulonglong2 wq_ = *(const ulonglong2*)(wr);
                        ulonglong2 wk_ = *(const ulonglong2*)(wr + 32);
                        ulonglong2 wv_ = *(const ulonglong2*)(wr + 64);
                        u64 d0 = dup2(xk0[kq]);
                        u64 d1 = dup2(xk1[kq]);
                        ffma2(aq[0][0], d0, wq_.x); ffma2(aq[0][1], d0, wq_.y);
                        ffma2(aq[1][0], d1, wq_.x); ffma2(aq[1][1], d1, wq_.y);
                        ffma2(ak[0][0], d0, wk_.x); ffma2(ak[0][1], d0, wk_.y);
                        ffma2(ak[1][0], d1, wk_.x); ffma2(ak[1][1], d1, wk_.y);
                        ffma2(av[0][0], d0, wv_.x); ffma2(av[0][1], d0, wv_.y);
                        ffma2(av[1][0], d1, wv_.x); ffma2(av[1][1], d1, wv_.y);
                    }
                }
                __syncthreads();   // all warps done reading buf before refill
                if (ch < NCHUNK - 2) {
                    const int cn = ch + 2;
                    for (int s = 0; s < nst; s++)
                        CP16(wbuf_u + (uint32_t)(((ch & 1) * WB_FLOATS + doff[s]) * 4),
                             sbase[s] + hd + cn * CHUNK_K * DIM);
                }
                CPCOMMIT();        // unconditional: keeps group accounting aligned
            }

            // biases + stores
            float4 bbq = *(const float4*)&bq[hd + c4];
            float4 bbk = *(const float4*)&bk[hd + c4];
            float4 bbv = *(const float4*)&bv[hd + c4];
#pragma unroll
            for (int r = 0; r < 2; r++) {
                float2 qlo = unpk(aq[r][0]), qhi = unpk(aq[r][1]);
                float2 vlo = unpk(av[r][0]), vhi = unpk(av[r][1]);
                *(float4*)&qh[(i0+r)*QS + c4] = make_float4(
                    qlo.x + bbq.x, qlo.y + bbq.y, qhi.x + bbq.z, qhi.y + bbq.w);
                *(float4*)&vh[(i0+r)*HDIM + c4] = make_float4(
                    vlo.x + bbv.x, vlo.y + bbv.y, vhi.x + bbv.z, vhi.y + bbv.w);
            }
            {
                float2 k0lo = unpk(ak[0][0]), k0hi = unpk(ak[0][1]);
                float2 k1lo = unpk(ak[1][0]), k1hi = unpk(ak[1][1]);
                // kt[col][row]: 2 consecutive rows -> float2 store per col
                *(float2*)&kt[(c4+0)*64 + i0] = make_float2(k0lo.x + bbk.x, k1lo.x + bbk.x);
                *(float2*)&kt[(c4+1)*64 + i0] = make_float2(k0lo.y + bbk.y, k1lo.y + bbk.y);
                *(float2*)&kt[(c4+2)*64 + i0] = make_float2(k0hi.x + bbk.z, k1hi.x + bbk.z);
                *(float2*)&kt[(c4+3)*64 + i0] = make_float2(k0hi.y + bbk.w, k1hi.y + bbk.w);
            }
        }
        __syncthreads();

        // ---- scores (packed): att[i][j] = (q_h[i] . k_h[j]) / sqrt(32) ----
        {
            const int i0 = (t >> 4) << 2;
            const int j0 = (t & 15) << 2;
            u64 a[4][2];
#pragma unroll
            for (int r = 0; r < 4; r++) { a[r][0] = 0ull; a[r][1] = 0ull; }
#pragma unroll
            for (int kk = 0; kk < HDIM; kk += 4) {
                ulonglong2 k0 = *(const ulonglong2*)&kt[(kk+0)*64 + j0];
                ulonglong2 k1 = *(const ulonglong2*)&kt[(kk+1)*64 + j0];
                ulonglong2 k2 = *(const ulonglong2*)&kt[(kk+2)*64 + j0];
                ulonglong2 k3 = *(const ulonglong2*)&kt[(kk+3)*64 + j0];
                float4 q0 = *(const float4*)&qh[(i0+0)*QS + kk];
                float4 q1 = *(const float4*)&qh[(i0+1)*QS + kk];
                float4 q2 = *(const float4*)&qh[(i0+2)*QS + kk];
                float4 q3 = *(const float4*)&qh[(i0+3)*QS + kk];
#pragma unroll
                for (int r = 0; r < 4; r++) {
                    float4 qr = (r==0) ? q0 : (r==1) ? q1 : (r==2) ? q2 : q3;
                    u64 d;
                    d = dup2(qr.x); ffma2(a[r][0], d, k0.x); ffma2(a[r][1], d, k0.y);
                    d = dup2(qr.y); ffma2(a[r][0], d, k1.x); ffma2(a[r][1], d, k1.y);
                    d = dup2(qr.z); ffma2(a[r][0], d, k2.x); ffma2(a[r][1], d, k2.y);
                    d = dup2(qr.w); ffma2(a[r][0], d, k3.x); ffma2(a[r][1], d, k3.y);
                }
            }
#pragma unroll
            for (int r = 0; r < 4; r++) {
                float2 lo = unpk(a[r][0]);
                float2 hi = unpk(a[r][1]);
                *(float4*)&att[(i0+r)*ATS + j0] = make_float4(
                    lo.x*inv_sqrt_d, lo.y*inv_sqrt_d, hi.x*inv_sqrt_d, hi.y*inv_sqrt_d);
            }
        }
        __syncthreads();

        // ---- softmax: 2 threads per row ----
        if (t < 128) {
            const int row  = t >> 1;
            const int half = (t & 1) << 5;
            float* rp = att + row * ATS + half;
            float m = rp[0];
#pragma unroll
            for (int j = 1; j < 32; j++) m = fmaxf(m, rp[j]);
            m = fmaxf(m, __shfl_xor_sync(0xFFFFFFFF, m, 1));
            float s = 0.f;
#pragma unroll
            for (int j = 0; j < 32; j++) { float e = __expf(rp[j] - m); rp[j] = e; s += e; }
            s += __shfl_xor_sync(0xFFFFFFFF, s, 1);
            float inv = 1.f / s;
#pragma unroll
            for (int j = 0; j < 32; j++) rp[j] *= inv;
        }
        __syncthreads();

        // ---- z head (packed): zh = att @ vh (zh reuses kt) ----
        float* zh = kt;
        {
            const int c4 = (t & 7) << 2;
            const int i0 = (t >> 3) << 1;
            u64 a0[2] = {0ull, 0ull};
            u64 a1[2] = {0ull, 0ull};
#pragma unroll 4
            for (int j = 0; j < NFEAT; j += 4) {
                float4 p0 = *(const float4*)&att[i0 * ATS + j];
                float4 p1 = *(const float4*)&att[(i0+1) * ATS + j];
                ulonglong2 v0 = *(const ulonglong2*)&vh[(j+0)*HDIM + c4];
                ulonglong2 v1 = *(const ulonglong2*)&vh[(j+1)*HDIM + c4];
                ulonglong2 v2 = *(const ulonglong2*)&vh[(j+2)*HDIM + c4];
                ulonglong2 v3 = *(const ulonglong2*)&vh[(j+3)*HDIM + c4];
                u64 d;
                d = dup2(p0.x); ffma2(a0[0], d, v0.x); ffma2(a0[1], d, v0.y);
                d = dup2(p0.y); ffma2(a0[0], d, v1.x); ffma2(a0[1], d, v1.y);
                d = dup2(p0.z); ffma2(a0[0], d, v2.x); ffma2(a0[1], d, v2.y);
                d = dup2(p0.w); ffma2(a0[0], d, v3.x); ffma2(a0[1], d, v3.y);
                d = dup2(p1.x); ffma2(a1[0], d, v0.x); ffma2(a1[1], d, v0.y);
                d = dup2(p1.y); ffma2(a1[0], d, v1.x); ffma2(a1[1], d, v1.y);
                d = dup2(p1.z); ffma2(a1[0], d, v2.x); ffma2(a1[1], d, v2.y);
                d = dup2(p1.w); ffma2(a1[0], d, v3.x); ffma2(a1[1], d, v3.y);
            }
            __syncthreads();  // everyone done READING kt (k data) before zh write
            float2 a0lo = unpk(a0[0]), a0hi = unpk(a0[1]);
            float2 a1lo = unpk(a1[0]), a1hi = unpk(a1[1]);
            *(float4*)&zh[i0 * HDIM + c4]     = make_float4(a0lo.x, a0lo.y, a0hi.x, a0hi.y);
            *(float4*)&zh[(i0+1) * HDIM + c4] = make_float4(a1lo.x, a1lo.y, a1hi.x, a1hi.y);
        }
        __syncthreads();

        // ---- facc += z_h @ W1[hd:hd+32, :] (packed) ----
        {
            const int jg = t & 63;
            const int i0 = (t >> 6) << 4;
            const float4* W14 = (const float4*)W1;
#pragma unroll
            for (int kk = 0; kk < HDIM; kk += 4) {
                ulonglong2 w0 = *(const ulonglong2*)&W14[((hd+kk+0) << 6) + jg];
                ulonglong2 w1 = *(const ulonglong2*)&W14[((hd+kk+1) << 6) + jg];
                ulonglong2 w2 = *(const ulonglong2*)&W14[((hd+kk+2) << 6) + jg];
                ulonglong2 w3 = *(const ulonglong2*)&W14[((hd+kk+3) << 6) + jg];
#pragma unroll
                for (int r = 0; r < 16; r++) {
                    float4 zv = *(const float4*)&zh[(i0+r) * HDIM + kk];
                    u64 d;
                    d = dup2(zv.x); ffma2(facc[r][0], d, w0.x); ffma2(facc[r][1], d, w0.y);
                    d = dup2(zv.y); ffma2(facc[r][0], d, w1.x); ffma2(facc[r][1], d, w1.y);
                    d = dup2(zv.z); ffma2(facc[r][0], d, w2.x); ffma2(facc[r][1], d, w2.y);
                    d = dup2(zv.w); ffma2(facc[r][0], d, w3.x); ffma2(facc[r][1], d, w3.y);
                }
            }
        }
        __syncthreads();  // protect zh/qh/vh/att before next head rewrites them
    }

    // ---- f = relu(facc + b1 + x); partial dot with W2 ----
    {
        const int jg = t & 63;
        const int i0 = (t >> 6) << 4;
        const int j0 = jg << 2;
        float4 b1v = ((const float4*)b1)[jg];
        float part = 0.f;
#pragma unroll
        for (int r = 0; r < 16; r++) {
            int i = i0 + r;
            float4 w2 = ((const float4*)W2)[(i << 6) + jg];
            float4 xv = *(const float4*)&xs[i * XS + j0];
            float2 flo = unpk(facc[r][0]);
            float2 fhi = unpk(facc[r][1]);
            float f0 = fmaxf(flo.x + b1v.x + xv.x, 0.f);
            float f1 = fmaxf(flo.y + b1v.y + xv.y, 0.f);
            float f2 = fmaxf(fhi.x + b1v.z + xv.z, 0.f);
            float f3 = fmaxf(fhi.y + b1v.w + xv.w, 0.f);
            part += f0*w2.x + f1*w2.y + f2*w2.z + f3*w2.w;
        }
        red[t] = part;
    }
    __syncthreads();

#pragma unroll
    for (int s = 128; s > 0; s >>= 1) {
        if (t < s) red[t] += red[t + s];
        __syncthreads();
    }
    if (t == 0) {
        out[b] = 1.f / (1.f + __expf(-(red[0] + b2[0])));
    }
}

extern "C" void kernel_launch(void* const* d_in, const int* in_sizes, int n_in,
                              void* d_out, int out_size)
{
    const float* x  = (const float*)d_in[0];
    const float* Wq = (const float*)d_in[1];
    const float* bq = (const float*)d_in[2];
    const float* Wk = (const float*)d_in[3];
    const float* bk = (const float*)d_in[4];
    const float* Wv = (const float*)d_in[5];
    const float* bv = (const float*)d_in[6];
    const float* W1 = (const float*)d_in[7];
    const float* b1 = (const float*)d_in[8];
    const float* W2 = (const float*)d_in[9];
    const float* b2 = (const float*)d_in[10];
    float* out = (float*)d_out;

    const int smem_bytes = SMEM_FLOATS * (int)sizeof(float); // 110,592 B -> 2 CTAs/SM
    cudaFuncSetAttribute(autoint_kernel,
                         cudaFuncAttributeMaxDynamicSharedMemorySize, smem_bytes);

    autoint_kernel<<<8192, 256, smem_bytes>>>(x, Wq, bq, Wk, bk, Wv, bv,
                                              W1, b1, W2, b2, out);
}